// round 4
// baseline (speedup 1.0000x reference)
#include <cuda_runtime.h>
#include <cstdint>

#define MAX_NODES 100000
#define DIM 64

// Scratch (no allocation allowed -> __device__ globals)
__device__ float g_S1[MAX_NODES * DIM];   // segsum of nfeats[src] by dst
__device__ float g_S2[MAX_NODES * DIM];   // segsum of efeats by dst
__device__ float g_deg[MAX_NODES];
__device__ float g_W[192 * DIM];          // [Wa_top ; C1 ; C2] row-major [192][64]
__device__ float g_cb[DIM];               // b_msg @ Wa_bot
__device__ float g_ba[DIM];               // b_apply

// ---------------------------------------------------------------------------
// Zero scratch
// ---------------------------------------------------------------------------
__global__ void zero_kernel(int n_nodes) {
    int i = blockIdx.x * blockDim.x + threadIdx.x;
    int n4 = n_nodes * 16;  // float4 count per S array
    float4 z = make_float4(0.f, 0.f, 0.f, 0.f);
    if (i < n4) {
        reinterpret_cast<float4*>(g_S1)[i] = z;
        reinterpret_cast<float4*>(g_S2)[i] = z;
    }
    if (i < n_nodes) g_deg[i] = 0.f;
}

// ---------------------------------------------------------------------------
// Fold weights: g_W = [Wa_top ; Wm_top@Wa_bot ; Wm_bot@Wa_bot], g_cb, g_ba
// ---------------------------------------------------------------------------
__global__ void fold_kernel(const float* __restrict__ Wm, const float* __restrict__ bm,
                            const float* __restrict__ Wa, const float* __restrict__ ba) {
    int idx = blockIdx.x * blockDim.x + threadIdx.x;
    if (idx < DIM) {
        float s = 0.f;
        for (int t = 0; t < DIM; t++) s += bm[t] * Wa[(DIM + t) * DIM + idx];
        g_cb[idx] = s;
        g_ba[idx] = ba[idx];
    }
    if (idx >= 192 * DIM) return;
    int k = idx / DIM;
    int j = idx % DIM;
    float v;
    if (k < 64) {
        v = Wa[k * DIM + j];                         // Wa_top
    } else {
        const float* wrow = (k < 128) ? &Wm[(k - 64) * DIM]
                                      : &Wm[(k - 128 + 64) * DIM];
        float s = 0.f;
        for (int t = 0; t < DIM; t++) s += wrow[t] * Wa[(DIM + t) * DIM + j];
        v = s;
    }
    g_W[idx] = v;
}

// ---------------------------------------------------------------------------
// Edge scatter: S1[dst] += nfeats[src]; S2[dst] += efeats[e]; deg[dst] += 1
// 16 threads per edge, each handles one float4 per matrix, vector red.
// ---------------------------------------------------------------------------
__device__ __forceinline__ void red4(float* p, float4 v) {
    asm volatile("red.global.add.v4.f32 [%0], {%1, %2, %3, %4};"
                 :: "l"(p), "f"(v.x), "f"(v.y), "f"(v.z), "f"(v.w) : "memory");
}

__global__ void scatter_kernel(const float4* __restrict__ nfeats4,
                               const float4* __restrict__ efeats4,
                               const int* __restrict__ src,
                               const int* __restrict__ dst,
                               int n_edges) {
    int e = blockIdx.x * 16 + (threadIdx.x >> 4);
    int lane = threadIdx.x & 15;
    if (e >= n_edges) return;
    int s = __ldg(&src[e]);
    int d = __ldg(&dst[e]);
    float4 a = nfeats4[(size_t)s * 16 + lane];
    float4 b = efeats4[(size_t)e * 16 + lane];
    red4(g_S1 + (size_t)d * DIM + lane * 4, a);
    red4(g_S2 + (size_t)d * DIM + lane * 4, b);
    if (lane == 0) atomicAdd(&g_deg[d], 1.0f);
}

// ---------------------------------------------------------------------------
// Node GEMM: out = relu([nf, S1*inv, S2*inv] @ g_W + ba + flag*cb)
// Block = 256 threads, 64 nodes/block. Dynamic smem: W (49152B) + X tile.
// ---------------------------------------------------------------------------
#define XS_STRIDE 196   // 192 + 4 pad: kills 8-way bank conflict on x reads

__global__ __launch_bounds__(256) void node_kernel(const float4* __restrict__ nfeats4,
                                                   float* __restrict__ out, int n_nodes) {
    extern __shared__ float sm[];
    float* Ws = sm;                 // [192][64]
    float* Xs = sm + 192 * DIM;     // [64][XS_STRIDE]
    __shared__ float s_bias[DIM];
    __shared__ float s_cb[DIM];
    __shared__ float s_flag[64];

    int tid = threadIdx.x;

    // load weights (3072 float4 / 256 threads = 12 each)
    {
        const float4* W4 = reinterpret_cast<const float4*>(g_W);
        float4* Ws4 = reinterpret_cast<float4*>(Ws);
        #pragma unroll
        for (int i = 0; i < 12; i++) Ws4[tid + i * 256] = W4[tid + i * 256];
    }
    if (tid < DIM) { s_bias[tid] = g_ba[tid]; s_cb[tid] = g_cb[tid]; }

    int row = tid >> 2;        // 0..63
    int l4  = tid & 3;         // 0..3
    int g   = blockIdx.x * 64 + row;
    bool valid = g < n_nodes;

    float degv = valid ? g_deg[g] : 0.f;
    float inv  = degv > 0.f ? (1.0f / degv) : 0.f;
    if (l4 == 0) s_flag[row] = (degv > 0.f) ? 1.f : 0.f;

    const float4* nf = nfeats4 + (size_t)g * 16;
    const float4* s1 = reinterpret_cast<const float4*>(g_S1) + (size_t)g * 16;
    const float4* s2 = reinterpret_cast<const float4*>(g_S2) + (size_t)g * 16;
    float* xrow = Xs + row * XS_STRIDE;
    float4 z = make_float4(0.f, 0.f, 0.f, 0.f);

    #pragma unroll
    for (int i = l4; i < 16; i += 4) {
        float4 v = valid ? nf[i] : z;
        *reinterpret_cast<float4*>(xrow + i * 4) = v;
        float4 a = valid ? s1[i] : z;
        a.x *= inv; a.y *= inv; a.z *= inv; a.w *= inv;
        *reinterpret_cast<float4*>(xrow + 64 + i * 4) = a;
        float4 b = valid ? s2[i] : z;
        b.x *= inv; b.y *= inv; b.z *= inv; b.w *= inv;
        *reinterpret_cast<float4*>(xrow + 128 + i * 4) = b;
    }
    __syncthreads();

    int jg = l4 * 16;
    float acc[16];
    float flag = s_flag[row];
    #pragma unroll
    for (int jj = 0; jj < 16; jj++) acc[jj] = s_bias[jg + jj] + flag * s_cb[jg + jj];

    for (int k = 0; k < 192; k += 4) {
        float4 xv = *reinterpret_cast<const float4*>(xrow + k);
        float xa[4] = {xv.x, xv.y, xv.z, xv.w};
        #pragma unroll
        for (int kk = 0; kk < 4; kk++) {
            float a = xa[kk];
            const float4* wr = reinterpret_cast<const float4*>(Ws + (k + kk) * DIM + jg);
            float4 w0 = wr[0], w1 = wr[1], w2 = wr[2], w3 = wr[3];
            acc[0]  += a * w0.x; acc[1]  += a * w0.y; acc[2]  += a * w0.z; acc[3]  += a * w0.w;
            acc[4]  += a * w1.x; acc[5]  += a * w1.y; acc[6]  += a * w1.z; acc[7]  += a * w1.w;
            acc[8]  += a * w2.x; acc[9]  += a * w2.y; acc[10] += a * w2.z; acc[11] += a * w2.w;
            acc[12] += a * w3.x; acc[13] += a * w3.y; acc[14] += a * w3.z; acc[15] += a * w3.w;
        }
    }

    if (valid) {
        float* o = out + (size_t)g * DIM + jg;
        #pragma unroll
        for (int q = 0; q < 4; q++) {
            float4 r;
            r.x = fmaxf(acc[q * 4 + 0], 0.f);
            r.y = fmaxf(acc[q * 4 + 1], 0.f);
            r.z = fmaxf(acc[q * 4 + 2], 0.f);
            r.w = fmaxf(acc[q * 4 + 3], 0.f);
            *reinterpret_cast<float4*>(o + q * 4) = r;
        }
    }
}

// ---------------------------------------------------------------------------
extern "C" void kernel_launch(void* const* d_in, const int* in_sizes, int n_in,
                              void* d_out, int out_size) {
    const float* nfeats = (const float*)d_in[0];
    const float* efeats = (const float*)d_in[1];
    const int*   src    = (const int*)d_in[2];
    const int*   dst    = (const int*)d_in[3];
    const float* Wm     = (const float*)d_in[4];
    const float* bm     = (const float*)d_in[5];
    const float* Wa     = (const float*)d_in[6];
    const float* ba     = (const float*)d_in[7];
    float* out = (float*)d_out;

    int n_nodes = in_sizes[0] / DIM;
    int n_edges = in_sizes[2];

    zero_kernel<<<(n_nodes * 16 + 255) / 256, 256>>>(n_nodes);
    fold_kernel<<<(192 * DIM + 255) / 256, 256>>>(Wm, bm, Wa, ba);
    scatter_kernel<<<(n_edges + 15) / 16, 256>>>(
        (const float4*)nfeats, (const float4*)efeats, src, dst, n_edges);

    int smem = 192 * DIM * 4 + 64 * XS_STRIDE * 4;  // 49152 + 50176 = 99328 B
    cudaFuncSetAttribute(node_kernel, cudaFuncAttributeMaxDynamicSharedMemorySize, smem);
    node_kernel<<<(n_nodes + 63) / 64, 256, smem>>>(
        (const float4*)nfeats, out, n_nodes);
}

// round 6
// speedup vs baseline: 1.3637x; 1.3637x over previous
#include <cuda_runtime.h>
#include <cstdint>

#define MAX_NODES 100000
#define DIM 64

__device__ float g_S1[MAX_NODES * DIM];   // segsum of nfeats[src] by dst
__device__ float g_S2[MAX_NODES * DIM];   // segsum of efeats by dst
__device__ float g_deg[MAX_NODES];
__device__ float g_W[192 * DIM];          // [Wa_top ; C1 ; C2] row-major [192][64]
__device__ float g_cb[DIM];               // b_msg @ Wa_bot
__device__ float g_ba[DIM];               // b_apply

// ---------------------------------------------------------------------------
__global__ void zero_kernel(int n_nodes) {
    int i = blockIdx.x * blockDim.x + threadIdx.x;
    int n4 = n_nodes * 16;
    float4 z = make_float4(0.f, 0.f, 0.f, 0.f);
    if (i < n4) {
        reinterpret_cast<float4*>(g_S1)[i] = z;
        reinterpret_cast<float4*>(g_S2)[i] = z;
    }
    if (i < n_nodes) g_deg[i] = 0.f;
}

// ---------------------------------------------------------------------------
__global__ void fold_kernel(const float* __restrict__ Wm, const float* __restrict__ bm,
                            const float* __restrict__ Wa, const float* __restrict__ ba) {
    int idx = blockIdx.x * blockDim.x + threadIdx.x;
    if (idx < DIM) {
        float s = 0.f;
        for (int t = 0; t < DIM; t++) s += bm[t] * Wa[(DIM + t) * DIM + idx];
        g_cb[idx] = s;
        g_ba[idx] = ba[idx];
    }
    if (idx >= 192 * DIM) return;
    int k = idx / DIM;
    int j = idx % DIM;
    float v;
    if (k < 64) {
        v = Wa[k * DIM + j];
    } else {
        const float* wrow = (k < 128) ? &Wm[(k - 64) * DIM]
                                      : &Wm[(k - 128 + 64) * DIM];
        float s = 0.f;
        for (int t = 0; t < DIM; t++) s += wrow[t] * Wa[(DIM + t) * DIM + j];
        v = s;
    }
    g_W[idx] = v;
}

// ---------------------------------------------------------------------------
__device__ __forceinline__ void red4(float* p, float4 v) {
    asm volatile("red.global.add.v4.f32 [%0], {%1, %2, %3, %4};"
                 :: "l"(p), "f"(v.x), "f"(v.y), "f"(v.z), "f"(v.w) : "memory");
}

__global__ void scatter_kernel(const float4* __restrict__ nfeats4,
                               const float4* __restrict__ efeats4,
                               const int* __restrict__ src,
                               const int* __restrict__ dst,
                               int n_edges) {
    int e = blockIdx.x * 16 + (threadIdx.x >> 4);
    int lane = threadIdx.x & 15;
    if (e >= n_edges) return;
    int s = __ldg(&src[e]);
    int d = __ldg(&dst[e]);
    float4 a = nfeats4[(size_t)s * 16 + lane];
    float4 b = efeats4[(size_t)e * 16 + lane];
    red4(g_S1 + (size_t)d * DIM + lane * 4, a);
    red4(g_S2 + (size_t)d * DIM + lane * 4, b);
    if (lane == 0) atomicAdd(&g_deg[d], 1.0f);
}

// ---------------------------------------------------------------------------
// Node GEMM v2: out = relu([nf, S1*inv, S2*inv] @ g_W + ba + flag*cb)
// 256 threads, 128 nodes/block. Each thread: 4 nodes x 8 outputs (32 accs).
// X staged TRANSPOSED (k-major) so one LDS.128 yields x[k] for 4 nodes.
// Per k: 1 x-LDS.128 + 2 W-LDS.128 + 32 FFMA  (ratio 1:10.7 vs 1:3.8 before).
// ---------------------------------------------------------------------------
#define NPB 128            // nodes per block
#define XT_STRIDE 132      // floats per k-row (128 nodes + 4 pad)

__global__ __launch_bounds__(256, 1) void node_kernel(const float4* __restrict__ nfeats4,
                                                      float* __restrict__ out, int n_nodes) {
    extern __shared__ float sm[];
    float* Ws  = sm;                    // [192][64]   49152 B
    float* XsT = sm + 192 * DIM;        // [192][132]  101376 B
    __shared__ float s_bias[DIM];
    __shared__ float s_cb[DIM];
    __shared__ float s_inv[NPB];
    __shared__ float s_flag[NPB];

    int tid  = threadIdx.x;
    int base = blockIdx.x * NPB;

    // load weights: 3072 float4 / 256 threads = 12 each
    {
        const float4* W4 = reinterpret_cast<const float4*>(g_W);
        float4* Ws4 = reinterpret_cast<float4*>(Ws);
        #pragma unroll
        for (int i = 0; i < 12; i++) Ws4[tid + i * 256] = W4[tid + i * 256];
    }
    if (tid < DIM) { s_bias[tid] = g_ba[tid]; s_cb[tid] = g_cb[tid]; }
    if (tid < NPB) {
        int g = base + tid;
        float degv = (g < n_nodes) ? g_deg[g] : 0.f;
        s_inv[tid]  = degv > 0.f ? (1.0f / degv) : 0.f;
        s_flag[tid] = degv > 0.f ? 1.f : 0.f;
    }
    __syncthreads();

    // Stage X transposed: XsT[k][node] for k in [0,192)
    {
        const float4* s14 = reinterpret_cast<const float4*>(g_S1);
        const float4* s24 = reinterpret_cast<const float4*>(g_S2);
        float4 z = make_float4(0.f, 0.f, 0.f, 0.f);
        for (int c = tid; c < NPB * 48; c += 256) {
            int node  = c / 48;
            int piece = c % 48;
            int g = base + node;
            bool valid = g < n_nodes;
            float4 v = z;
            int kbase;
            if (piece < 16) {
                if (valid) v = nfeats4[(size_t)g * 16 + piece];
                kbase = piece * 4;
            } else if (piece < 32) {
                int p = piece - 16;
                if (valid) {
                    v = s14[(size_t)g * 16 + p];
                    float iv = s_inv[node];
                    v.x *= iv; v.y *= iv; v.z *= iv; v.w *= iv;
                }
                kbase = 64 + p * 4;
            } else {
                int p = piece - 32;
                if (valid) {
                    v = s24[(size_t)g * 16 + p];
                    float iv = s_inv[node];
                    v.x *= iv; v.y *= iv; v.z *= iv; v.w *= iv;
                }
                kbase = 128 + p * 4;
            }
            XsT[(kbase + 0) * XT_STRIDE + node] = v.x;
            XsT[(kbase + 1) * XT_STRIDE + node] = v.y;
            XsT[(kbase + 2) * XT_STRIDE + node] = v.z;
            XsT[(kbase + 3) * XT_STRIDE + node] = v.w;
        }
    }
    __syncthreads();

    int grp = tid >> 3;        // 0..31 : node-quad index
    int l8  = tid & 7;         // 0..7  : output octet
    int jg  = l8 * 8;

    float acc[4][8];
    #pragma unroll
    for (int n = 0; n < 4; n++) {
        float flag = s_flag[grp * 4 + n];
        #pragma unroll
        for (int j = 0; j < 8; j++) acc[n][j] = s_bias[jg + j] + flag * s_cb[jg + j];
    }

    #pragma unroll 4
    for (int k = 0; k < 192; k++) {
        float4 xv = *reinterpret_cast<const float4*>(XsT + k * XT_STRIDE + grp * 4);
        const float4* wr = reinterpret_cast<const float4*>(Ws + k * DIM + jg);
        float4 w0 = wr[0], w1 = wr[1];
        float xa[4] = {xv.x, xv.y, xv.z, xv.w};
        #pragma unroll
        for (int n = 0; n < 4; n++) {
            float a = xa[n];
            acc[n][0] += a * w0.x; acc[n][1] += a * w0.y;
            acc[n][2] += a * w0.z; acc[n][3] += a * w0.w;
            acc[n][4] += a * w1.x; acc[n][5] += a * w1.y;
            acc[n][6] += a * w1.z; acc[n][7] += a * w1.w;
        }
    }

    #pragma unroll
    for (int n = 0; n < 4; n++) {
        int g = base + grp * 4 + n;
        if (g < n_nodes) {
            float* o = out + (size_t)g * DIM + jg;
            float4 r0, r1;
            r0.x = fmaxf(acc[n][0], 0.f); r0.y = fmaxf(acc[n][1], 0.f);
            r0.z = fmaxf(acc[n][2], 0.f); r0.w = fmaxf(acc[n][3], 0.f);
            r1.x = fmaxf(acc[n][4], 0.f); r1.y = fmaxf(acc[n][5], 0.f);
            r1.z = fmaxf(acc[n][6], 0.f); r1.w = fmaxf(acc[n][7], 0.f);
            *reinterpret_cast<float4*>(o)     = r0;
            *reinterpret_cast<float4*>(o + 4) = r1;
        }
    }
}

// ---------------------------------------------------------------------------
extern "C" void kernel_launch(void* const* d_in, const int* in_sizes, int n_in,
                              void* d_out, int out_size) {
    const float* nfeats = (const float*)d_in[0];
    const float* efeats = (const float*)d_in[1];
    const int*   src    = (const int*)d_in[2];
    const int*   dst    = (const int*)d_in[3];
    const float* Wm     = (const float*)d_in[4];
    const float* bm     = (const float*)d_in[5];
    const float* Wa     = (const float*)d_in[6];
    const float* ba     = (const float*)d_in[7];
    float* out = (float*)d_out;

    int n_nodes = in_sizes[0] / DIM;
    int n_edges = in_sizes[2];

    zero_kernel<<<(n_nodes * 16 + 255) / 256, 256>>>(n_nodes);
    fold_kernel<<<(192 * DIM + 255) / 256, 256>>>(Wm, bm, Wa, ba);
    scatter_kernel<<<(n_edges + 15) / 16, 256>>>(
        (const float4*)nfeats, (const float4*)efeats, src, dst, n_edges);

    int smem = 192 * DIM * 4 + 192 * XT_STRIDE * 4;  // 49152 + 101376 = 150528 B
    cudaFuncSetAttribute(node_kernel, cudaFuncAttributeMaxDynamicSharedMemorySize, smem);
    node_kernel<<<(n_nodes + NPB - 1) / NPB, 256, smem>>>(
        (const float4*)nfeats, out, n_nodes);
}

// round 9
// speedup vs baseline: 1.5492x; 1.1360x over previous
#include <cuda_runtime.h>
#include <cstdint>

#define MAX_NODES 100000
#define DIM 64

__device__ float g_S1[MAX_NODES * DIM];   // segsum of nfeats[src] by dst
__device__ float g_S2[MAX_NODES * DIM];   // segsum of efeats by dst
__device__ float g_deg[MAX_NODES];
__device__ float g_W[192 * DIM];          // [Wa_top ; C1 ; C2] row-major [192][64]
__device__ float g_cb[DIM];               // b_msg @ Wa_bot
__device__ float g_ba[DIM];               // b_apply

// ---------------------------------------------------------------------------
__global__ void zero_kernel(int n_nodes) {
    int i = blockIdx.x * blockDim.x + threadIdx.x;
    int n4 = n_nodes * 16;
    float4 z = make_float4(0.f, 0.f, 0.f, 0.f);
    if (i < n4) {
        reinterpret_cast<float4*>(g_S1)[i] = z;
        reinterpret_cast<float4*>(g_S2)[i] = z;
    }
    if (i < n_nodes) g_deg[i] = 0.f;
}

// ---------------------------------------------------------------------------
__global__ void fold_kernel(const float* __restrict__ Wm, const float* __restrict__ bm,
                            const float* __restrict__ Wa, const float* __restrict__ ba) {
    int idx = blockIdx.x * blockDim.x + threadIdx.x;
    if (idx < DIM) {
        float s = 0.f;
        for (int t = 0; t < DIM; t++) s += bm[t] * Wa[(DIM + t) * DIM + idx];
        g_cb[idx] = s;
        g_ba[idx] = ba[idx];
    }
    if (idx >= 192 * DIM) return;
    int k = idx / DIM;
    int j = idx % DIM;
    float v;
    if (k < 64) {
        v = Wa[k * DIM + j];
    } else {
        const float* wrow = (k < 128) ? &Wm[(k - 64) * DIM]
                                      : &Wm[(k - 128 + 64) * DIM];
        float s = 0.f;
        for (int t = 0; t < DIM; t++) s += wrow[t] * Wa[(DIM + t) * DIM + j];
        v = s;
    }
    g_W[idx] = v;
}

// ---------------------------------------------------------------------------
__device__ __forceinline__ void red4(float* p, float4 v) {
    asm volatile("red.global.add.v4.f32 [%0], {%1, %2, %3, %4};"
                 :: "l"(p), "f"(v.x), "f"(v.y), "f"(v.z), "f"(v.w) : "memory");
}

__global__ void scatter_kernel(const float4* __restrict__ nfeats4,
                               const float4* __restrict__ efeats4,
                               const int* __restrict__ src,
                               const int* __restrict__ dst,
                               int n_edges) {
    int e = blockIdx.x * 16 + (threadIdx.x >> 4);
    int lane = threadIdx.x & 15;
    if (e >= n_edges) return;
    int s = __ldg(&src[e]);
    int d = __ldg(&dst[e]);
    float4 a = nfeats4[(size_t)s * 16 + lane];
    float4 b = efeats4[(size_t)e * 16 + lane];
    red4(g_S1 + (size_t)d * DIM + lane * 4, a);
    red4(g_S2 + (size_t)d * DIM + lane * 4, b);
    if (lane == 0) atomicAdd(&g_deg[d], 1.0f);
}

// ---------------------------------------------------------------------------
// Node GEMM v3: 256 thr, 128 nodes/block, 4 nodes x 8 outputs per thread.
// K split into 2 chunks of 96 staged into ONE XsT buffer -> smem 99.8KB
// -> 2 blocks/SM (16 warps) vs v2's 1 block (8 warps).
// ---------------------------------------------------------------------------
#define NPB 128            // nodes per block
#define KCH 96             // k rows per chunk (2 chunks of 96 = 192)
#define XT_STRIDE 132      // floats per k-row (128 nodes + 4 pad)

__global__ __launch_bounds__(256, 2) void node_kernel(const float4* __restrict__ nfeats4,
                                                      float* __restrict__ out, int n_nodes) {
    extern __shared__ float sm[];
    float* Ws  = sm;                    // [192][64]  49152 B
    float* XsT = sm + 192 * DIM;        // [96][132]  50688 B
    __shared__ float s_bias[DIM];
    __shared__ float s_cb[DIM];
    __shared__ float s_inv[NPB];
    __shared__ float s_flag[NPB];

    int tid  = threadIdx.x;
    int base = blockIdx.x * NPB;

    // load weights: 3072 float4 / 256 threads = 12 each
    {
        const float4* W4 = reinterpret_cast<const float4*>(g_W);
        float4* Ws4 = reinterpret_cast<float4*>(Ws);
        #pragma unroll
        for (int i = 0; i < 12; i++) Ws4[tid + i * 256] = W4[tid + i * 256];
    }
    if (tid < DIM) { s_bias[tid] = g_ba[tid]; s_cb[tid] = g_cb[tid]; }
    if (tid < NPB) {
        int g = base + tid;
        float degv = (g < n_nodes) ? g_deg[g] : 0.f;
        s_inv[tid]  = degv > 0.f ? (1.0f / degv) : 0.f;
        s_flag[tid] = degv > 0.f ? 1.f : 0.f;
    }
    __syncthreads();

    int grp = tid >> 3;        // 0..31 : node-quad index
    int l8  = tid & 7;         // 0..7  : output octet
    int jg  = l8 * 8;

    float acc[4][8];
    #pragma unroll
    for (int n = 0; n < 4; n++) {
        float flag = s_flag[grp * 4 + n];
        #pragma unroll
        for (int j = 0; j < 8; j++) acc[n][j] = s_bias[jg + j] + flag * s_cb[jg + j];
    }

    const float4* s14 = reinterpret_cast<const float4*>(g_S1);
    const float4* s24 = reinterpret_cast<const float4*>(g_S2);
    float4 z = make_float4(0.f, 0.f, 0.f, 0.f);

    #pragma unroll
    for (int chunk = 0; chunk < 2; chunk++) {
        // ---- stage 96 k-rows (24 float4 pieces per node) ----
        for (int c = tid; c < NPB * 24; c += 256) {
            int node  = c / 24;
            int piece = c % 24;
            int g = base + node;
            bool valid = g < n_nodes;
            float4 v = z;
            int kbase;
            if (chunk == 0) {
                if (piece < 16) {               // nfeats k 0..63
                    if (valid) v = nfeats4[(size_t)g * 16 + piece];
                    kbase = piece * 4;
                } else {                        // s1 pieces 0..7 -> k 64..95
                    int p = piece - 16;
                    if (valid) {
                        v = s14[(size_t)g * 16 + p];
                        float iv = s_inv[node];
                        v.x *= iv; v.y *= iv; v.z *= iv; v.w *= iv;
                    }
                    kbase = 64 + p * 4;
                }
            } else {
                if (piece < 8) {                // s1 pieces 8..15 -> global k 96..127
                    int q = piece + 8;
                    if (valid) {
                        v = s14[(size_t)g * 16 + q];
                        float iv = s_inv[node];
                        v.x *= iv; v.y *= iv; v.z *= iv; v.w *= iv;
                    }
                    kbase = piece * 4;          // local 0..31
                } else {                        // s2 pieces 0..15 -> global k 128..191
                    int q = piece - 8;
                    if (valid) {
                        v = s24[(size_t)g * 16 + q];
                        float iv = s_inv[node];
                        v.x *= iv; v.y *= iv; v.z *= iv; v.w *= iv;
                    }
                    kbase = 32 + q * 4;         // local 32..95
                }
            }
            XsT[(kbase + 0) * XT_STRIDE + node] = v.x;
            XsT[(kbase + 1) * XT_STRIDE + node] = v.y;
            XsT[(kbase + 2) * XT_STRIDE + node] = v.z;
            XsT[(kbase + 3) * XT_STRIDE + node] = v.w;
        }
        __syncthreads();

        // ---- compute 96 k-rows ----
        const float* Wchunk = Ws + chunk * KCH * DIM;
        #pragma unroll 4
        for (int k = 0; k < KCH; k++) {
            float4 xv = *reinterpret_cast<const float4*>(XsT + k * XT_STRIDE + grp * 4);
            const float4* wr = reinterpret_cast<const float4*>(Wchunk + k * DIM + jg);
            float4 w0 = wr[0], w1 = wr[1];
            float xa[4] = {xv.x, xv.y, xv.z, xv.w};
            #pragma unroll
            for (int n = 0; n < 4; n++) {
                float a = xa[n];
                acc[n][0] += a * w0.x; acc[n][1] += a * w0.y;
                acc[n][2] += a * w0.z; acc[n][3] += a * w0.w;
                acc[n][4] += a * w1.x; acc[n][5] += a * w1.y;
                acc[n][6] += a * w1.z; acc[n][7] += a * w1.w;
            }
        }
        __syncthreads();
    }

    #pragma unroll
    for (int n = 0; n < 4; n++) {
        int g = base + grp * 4 + n;
        if (g < n_nodes) {
            float* o = out + (size_t)g * DIM + jg;
            float4 r0, r1;
            r0.x = fmaxf(acc[n][0], 0.f); r0.y = fmaxf(acc[n][1], 0.f);
            r0.z = fmaxf(acc[n][2], 0.f); r0.w = fmaxf(acc[n][3], 0.f);
            r1.x = fmaxf(acc[n][4], 0.f); r1.y = fmaxf(acc[n][5], 0.f);
            r1.z = fmaxf(acc[n][6], 0.f); r1.w = fmaxf(acc[n][7], 0.f);
            *reinterpret_cast<float4*>(o)     = r0;
            *reinterpret_cast<float4*>(o + 4) = r1;
        }
    }
}

// ---------------------------------------------------------------------------
extern "C" void kernel_launch(void* const* d_in, const int* in_sizes, int n_in,
                              void* d_out, int out_size) {
    const float* nfeats = (const float*)d_in[0];
    const float* efeats = (const float*)d_in[1];
    const int*   src    = (const int*)d_in[2];
    const int*   dst    = (const int*)d_in[3];
    const float* Wm     = (const float*)d_in[4];
    const float* bm     = (const float*)d_in[5];
    const float* Wa     = (const float*)d_in[6];
    const float* ba     = (const float*)d_in[7];
    float* out = (float*)d_out;

    int n_nodes = in_sizes[0] / DIM;
    int n_edges = in_sizes[2];

    zero_kernel<<<(n_nodes * 16 + 255) / 256, 256>>>(n_nodes);
    fold_kernel<<<(192 * DIM + 255) / 256, 256>>>(Wm, bm, Wa, ba);
    scatter_kernel<<<(n_edges + 15) / 16, 256>>>(
        (const float4*)nfeats, (const float4*)efeats, src, dst, n_edges);

    int smem = 192 * DIM * 4 + KCH * XT_STRIDE * 4;  // 49152 + 50688 = 99840 B
    cudaFuncSetAttribute(node_kernel, cudaFuncAttributeMaxDynamicSharedMemorySize, smem);
    node_kernel<<<(n_nodes + NPB - 1) / NPB, 256, smem>>>(
        (const float4*)nfeats, out, n_nodes);
}